// round 16
// baseline (speedup 1.0000x reference)
#include <cuda_runtime.h>
#include <cuda_fp16.h>
#include <math.h>
#include <stdint.h>

#define B 8
#define L1 384
#define L2 384
#define H 128
#define H2 256
#define H4 512
#define NFLAGS 192   // 24 t-chunks x 8 batches

// ---- scratch (allocation-free: __device__ globals) ----
__device__ float d_xp[B * L1 * H];
__device__ float d_yp[B * L2 * H];
__device__ float d_s [B * L1 * L2];
__device__ float d_gx[B * L1 * H4];
__device__ int   d_flags[NFLAGS];

__device__ __forceinline__ float tanh_fast(float x) {
    float y;
    asm("tanh.approx.f32 %0, %1;" : "=f"(y) : "f"(x));
    return y;
}
__device__ __forceinline__ float sigmoid_acc(float x) {
    x = fminf(fmaxf(x, -30.f), 30.f);
    return 1.f / (1.f + __expf(-x));
}
__device__ __forceinline__ float tanh_acc(float x) {
    x = fminf(fmaxf(x, -15.f), 15.f);
    float e = __expf(-2.f * x);
    return (1.f - e) / (1.f + e);
}

// ============================================================
// Kernel A: row projections (+ flag reset, stream-ordered before fused)
// ============================================================
__global__ void k_proj(const float* __restrict__ x, const float* __restrict__ y,
                       const float* __restrict__ Wup, const float* __restrict__ bup,
                       const float* __restrict__ Wq,  const float* __restrict__ bq,
                       const float* __restrict__ bvp)
{
    int row = blockIdx.x;
    int o   = threadIdx.x;

    // reset pipeline flags for this replay
    if (row == 0 && o < 128)            d_flags[o] = 0;
    if (row == 1 && o < NFLAGS - 128)   d_flags[128 + o] = 0;

    __shared__ float4 in4[H / 4];
    const float* in; const float* W; float bias; float* out;
    if (row < B * L1) {
        in = x + (size_t)row * H;  W = Wup;  bias = bup[o];           out = d_xp + (size_t)row * H;
    } else {
        int r = row - B * L1;
        in = y + (size_t)r * H;    W = Wq;   bias = bq[o] + bvp[o];   out = d_yp + (size_t)r * H;
    }
    if (o < H / 4) in4[o] = ((const float4*)in)[o];
    __syncthreads();

    const float4* W4 = (const float4*)(W + (size_t)o * H);
    float acc = bias;
#pragma unroll
    for (int k = 0; k < H / 4; k++) {
        float4 w = W4[k];
        float4 v = in4[k];
        acc += w.x * v.x + w.y * v.y + w.z * v.z + w.w * v.w;
    }
    out[o] = acc;
}

// ============================================================
// Kernel B: additive attention scores (MUFU-bound, full-chip parallel)
// ============================================================
__global__ void k_scores(const unsigned char* __restrict__ xmask,
                         const unsigned char* __restrict__ ymask,
                         const float* __restrict__ Vw, const float* __restrict__ Vb)
{
    int b  = blockIdx.z;
    int t0 = blockIdx.y * 32;
    int j0 = blockIdx.x * 32;

    __shared__ float4 xs[32 * 32];
    __shared__ float4 ys[32 * 33];
    __shared__ float4 vs[32];

    int tid = threadIdx.y * 32 + threadIdx.x;
    for (int i = tid; i < 32 * 32; i += 256) {
        int r = i >> 5, k = i & 31;
        xs[r * 32 + k] = ((const float4*)(d_xp + (size_t)((b * L1) + t0 + r) * H))[k];
        ys[r * 33 + k] = ((const float4*)(d_yp + (size_t)((b * L2) + j0 + r) * H))[k];
    }
    if (tid < 32) vs[tid] = ((const float4*)Vw)[tid];
    __syncthreads();

    int j = threadIdx.x;
    float acc[4] = {0.f, 0.f, 0.f, 0.f};

#pragma unroll 4
    for (int k = 0; k < 32; k++) {
        float4 yv = ys[j * 33 + k];
        float4 v  = vs[k];
#pragma unroll
        for (int i = 0; i < 4; i++) {
            float4 xv = xs[(threadIdx.y + i * 8) * 32 + k];
            acc[i] += v.x * tanh_fast(xv.x + yv.x);
            acc[i] += v.y * tanh_fast(xv.y + yv.y);
            acc[i] += v.z * tanh_fast(xv.z + yv.z);
            acc[i] += v.w * tanh_fast(xv.w + yv.w);
        }
    }

    bool  ymb = ymask[b * L2 + j0 + j] != 0;
    float ymv = ymb ? 0.f : 1.f;
    float vb  = Vb[0];
    const float NEG_INF = __int_as_float(0xff800000);
#pragma unroll
    for (int i = 0; i < 4; i++) {
        int t   = t0 + threadIdx.y + i * 8;
        float xm = (xmask[b * L1 + t] != 0) ? 0.f : 1.f;
        float s  = (acc[i] + vb) * (xm * ymv);
        if (ymb) s = NEG_INF;
        d_s[(size_t)((b * L1) + t) * L2 + j0 + j] = s;
    }
}

// ============================================================
// Kernel C: softmax over j
// ============================================================
__global__ void k_softmax()
{
    int row = blockIdx.x;
    float* s = d_s + (size_t)row * L2;
    int tid = threadIdx.x;   // 128

    float v[3];
    float m = -INFINITY;
#pragma unroll
    for (int i = 0; i < 3; i++) { v[i] = s[tid + i * 128]; m = fmaxf(m, v[i]); }

    __shared__ float red[4];
#pragma unroll
    for (int o = 16; o > 0; o >>= 1) m = fmaxf(m, __shfl_xor_sync(~0u, m, o));
    if ((tid & 31) == 0) red[tid >> 5] = m;
    __syncthreads();
    m = fmaxf(fmaxf(red[0], red[1]), fmaxf(red[2], red[3]));

    float sum = 0.f;
#pragma unroll
    for (int i = 0; i < 3; i++) { v[i] = __expf(v[i] - m); sum += v[i]; }
#pragma unroll
    for (int o = 16; o > 0; o >>= 1) sum += __shfl_xor_sync(~0u, sum, o);
    __shared__ float red2[4];
    if ((tid & 31) == 0) red2[tid >> 5] = sum;
    __syncthreads();
    sum = red2[0] + red2[1] + red2[2] + red2[3];

    float inv = 1.0f / sum;
#pragma unroll
    for (int i = 0; i < 3; i++) s[tid + i * 128] = v[i] * inv;
}

// ============================================================
// Kernel FUSED: producer/consumer pipeline (R14 skeleton).
// blocks 0..7   : LSTM (one batch each), consumes d_gx chunk-by-chunk.
// blocks 8..103 : workers; 16-row (b,t)-chunks in t-order:
//                 ctx (smem-only) -> merge -> gate -> gx -> release flag.
// LSTM dot upgraded: LDS.128 h loads (16/thread/step) + 16 chains of
// depth 4 (was 8x8) + dual f32 accumulators -> better latency hiding.
// ============================================================
__global__ void __launch_bounds__(512, 1)
k_fused(const float* __restrict__ x, const float* __restrict__ y,
        const float* __restrict__ Wg,  const float* __restrict__ bg,
        const float* __restrict__ Wih, const float* __restrict__ bih,
        const float* __restrict__ bhh,
        const float* __restrict__ Whh, float* __restrict__ out)
{
    __shared__ __align__(16) unsigned char sbuf[41984];
    int tid = threadIdx.x;

    if (blockIdx.x < 8) {
        // =============== LSTM consumer ===============
        __half* hs = (__half*)sbuf;                // 256B, 16B-aligned
        float*  gs = (float*)(sbuf + 256);         // 2KB
        int b = blockIdx.x;
        int t = tid;

        // one-time: pack this gate's 128 W_hh weights into 32 uint2 regs
        uint2 wreg[32];
        {
            const float4* wr = (const float4*)(Whh + (size_t)t * H);
#pragma unroll
            for (int kk = 0; kk < 32; kk++) {
                float4 w = wr[kk];
                half2 lo = __floats2half2_rn(w.x, w.y);
                half2 hi = __floats2half2_rn(w.z, w.w);
                wreg[kk].x = *(uint32_t*)&lo;
                wreg[kk].y = *(uint32_t*)&hi;
            }
        }

        if (t < H) hs[t] = __float2half_rn(0.f);
        float c = 0.f;
        const float* __restrict__ gxp = d_gx + (size_t)b * L1 * H4 + t;
        bool is_tanh_gate = ((t >> 7) == 2);
        __syncthreads();
        const uint4* h4p = (const uint4*)hs;       // 16 x 16B (8 halves each)

        float gx = 0.f;
        for (int step = 0; step < L1; step++) {
            if ((step & 15) == 0) {
                if (t == 0) {
                    const int* fp = &d_flags[(step >> 4) * 8 + b];
                    int v;
                    do {
                        asm volatile("ld.acquire.gpu.global.b32 %0, [%1];"
                                     : "=r"(v) : "l"(fp) : "memory");
                    } while (v == 0);
                }
                __syncthreads();
                gx = gxp[(size_t)step * H4];
            }
            float gpre = gx;
            if ((step & 15) != 15)
                gx = gxp[(size_t)(step + 1) * H4];   // prefetch (stays in chunk)

            // dot: 16 LDS.128, 16 chains of depth 4, dual f32 accumulators
            float f0 = 0.f, f1 = 0.f;
#pragma unroll
            for (int ch = 0; ch < 8; ch++) {
                uint4 hv0 = h4p[2 * ch];
                uint4 hv1 = h4p[2 * ch + 1];
                __half2 accA = __float2half2_rn(0.f);
                __half2 accB = __float2half2_rn(0.f);
                accA = __hfma2(*(const __half2*)&wreg[4 * ch + 0].x, *(const __half2*)&hv0.x, accA);
                accB = __hfma2(*(const __half2*)&wreg[4 * ch + 0].y, *(const __half2*)&hv0.y, accB);
                accA = __hfma2(*(const __half2*)&wreg[4 * ch + 1].x, *(const __half2*)&hv0.z, accA);
                accB = __hfma2(*(const __half2*)&wreg[4 * ch + 1].y, *(const __half2*)&hv0.w, accB);
                accA = __hfma2(*(const __half2*)&wreg[4 * ch + 2].x, *(const __half2*)&hv1.x, accA);
                accB = __hfma2(*(const __half2*)&wreg[4 * ch + 2].y, *(const __half2*)&hv1.y, accB);
                accA = __hfma2(*(const __half2*)&wreg[4 * ch + 3].x, *(const __half2*)&hv1.z, accA);
                accB = __hfma2(*(const __half2*)&wreg[4 * ch + 3].y, *(const __half2*)&hv1.w, accB);
                float2 fa = __half22float2(accA);
                float2 fb = __half22float2(accB);
                f0 += fa.x + fa.y;
                f1 += fb.x + fb.y;
            }
            gpre += f0 + f1;

            gs[t] = is_tanh_gate ? tanh_acc(gpre) : sigmoid_acc(gpre);
            __syncthreads();

            if (t < H) {
                float gi = gs[t], gf = gs[t + H], gg = gs[t + 2 * H], go = gs[t + 3 * H];
                c = gf * c + gi * gg;
                float hn = go * tanh_acc(c);
                hs[t] = __float2half_rn(hn);
                out[(size_t)((b * L1) + step) * H + t] = hn;
            }
            __syncthreads();
        }
        return;
    }

    // =============== worker producer (R14 structure) ===============
    float* ysm  = (float*)sbuf;                    // 16 j x 128 h  (8KB)
    float* alph = (float*)(sbuf + 8192);           // 16 r x 16 j   (1KB)
    float* ms   = (float*)(sbuf + 9216);           // 16 r x 256    (16KB)
    float* lis  = (float*)(sbuf + 9216 + 16384);   // 16 r x 256    (16KB)

    int w = blockIdx.x - 8;                        // 0..95
    for (int half = 0; half < 2; half++) {
        int cidx = w + half * 96;                  // chunk, t-ordered
        int tc = cidx >> 3;
        int b  = cidx & 7;
        int t0 = tc * 16;

        // ---- ctx: acc[4] over 24 chunks of 16 j ----
        int h  = tid & 127;
        int tg = tid >> 7;                         // 0..3 -> 4 rows each
        float acc[4] = {0.f, 0.f, 0.f, 0.f};

        const float4* y4 = (const float4*)(y + (size_t)b * L2 * H);
        const float*  sp = d_s + (size_t)(b * L1 + t0) * L2;

        float4 ybuf = y4[tid];
        float  abuf = (tid < 256) ? sp[(size_t)(tid >> 4) * L2 + (tid & 15)] : 0.f;

        for (int cj = 0; cj < 24; cj++) {
            __syncthreads();
            ((float4*)ysm)[tid] = ybuf;
            if (tid < 256) alph[tid] = abuf;
            __syncthreads();

            if (cj + 1 < 24) {
                ybuf = y4[(cj + 1) * 512 + tid];
                if (tid < 256)
                    abuf = sp[(size_t)(tid >> 4) * L2 + (cj + 1) * 16 + (tid & 15)];
            }

#pragma unroll 8
            for (int jj = 0; jj < 16; jj++) {
                float yv = ysm[jj * 128 + h];
#pragma unroll
                for (int i = 0; i < 4; i++)
                    acc[i] += alph[(tg * 4 + i) * 16 + jj] * yv;
            }
        }
        __syncthreads();

        // ---- merge tile: x cols [0,128), ct cols [128,256) ----
#pragma unroll
        for (int i = 0; i < 4; i++)
            ms[(tg * 4 + i) * 256 + 128 + h] = acc[i];
        for (int i = tid; i < 16 * 128; i += 512) {
            int r = i >> 7, k = i & 127;
            ms[r * 256 + k] = x[(size_t)(b * L1 + t0 + r) * H + k];
        }
        __syncthreads();

        // ---- gate: lis = sigmoid(ms @ Wg^T + bg) * ms ----
        {
            int rg = tid >> 8;                     // 0..1 -> 8 rows each
            int cc = tid & 255;
            float a8[8];
#pragma unroll
            for (int r = 0; r < 8; r++) a8[r] = 0.f;

            const float4* W4  = (const float4*)(Wg + (size_t)cc * H2);
            const float4* ms4 = (const float4*)ms;
            for (int k = 0; k < H2 / 4; k++) {
                float4 wv = W4[k];
#pragma unroll
                for (int r = 0; r < 8; r++) {
                    float4 m = ms4[(rg * 8 + r) * (H2 / 4) + k];
                    a8[r] += wv.x * m.x + wv.y * m.y + wv.z * m.z + wv.w * m.w;
                }
            }
            float bias = bg[cc];
#pragma unroll
            for (int r = 0; r < 8; r++) {
                float g = 1.0f / (1.0f + __expf(-(a8[r] + bias)));
                lis[(rg * 8 + r) * 256 + cc] = g * ms[(rg * 8 + r) * 256 + cc];
            }
        }
        __syncthreads();

        // ---- gx = lis @ W_ih^T + (b_ih + b_hh), one col per thread ----
        {
            int col = tid;                         // 0..511
            float a16[16];
#pragma unroll
            for (int r = 0; r < 16; r++) a16[r] = 0.f;

            const float4* Wv  = (const float4*)(Wih + (size_t)col * H2);
            const float4* li4 = (const float4*)lis;
            for (int k = 0; k < H2 / 4; k++) {
                float4 wv = Wv[k];
#pragma unroll
                for (int r = 0; r < 16; r++) {
                    float4 m = li4[r * (H2 / 4) + k];
                    a16[r] += wv.x * m.x + wv.y * m.y + wv.z * m.z + wv.w * m.w;
                }
            }
            float bias = bih[col] + bhh[col];
#pragma unroll
            for (int r = 0; r < 16; r++)
                d_gx[(size_t)(b * L1 + t0 + r) * H4 + col] = a16[r] + bias;
        }
        __syncthreads();

        if (tid == 0) {
            asm volatile("st.release.gpu.global.b32 [%0], %1;"
                         :: "l"(&d_flags[cidx]), "r"(1) : "memory");
        }
        __syncthreads();
    }
}

// ============================================================
extern "C" void kernel_launch(void* const* d_in, const int* in_sizes, int n_in,
                              void* d_out, int out_size)
{
    const float*         x     = (const float*)d_in[0];
    const unsigned char* xmask = (const unsigned char*)d_in[1];
    const float*         y     = (const float*)d_in[2];
    const unsigned char* ymask = (const unsigned char*)d_in[3];
    const float* Wq_w  = (const float*)d_in[4];
    const float* Wq_b  = (const float*)d_in[5];
    const float* Wup_w = (const float*)d_in[6];
    const float* Wup_b = (const float*)d_in[7];
    // d_in[8] = Wvp_w (multiplied by zeros in reference -> unused)
    const float* Wvp_b = (const float*)d_in[9];
    const float* V_w   = (const float*)d_in[10];
    const float* V_b   = (const float*)d_in[11];
    const float* Wg_w  = (const float*)d_in[12];
    const float* Wg_b  = (const float*)d_in[13];
    const float* W_ih  = (const float*)d_in[14];
    const float* W_hh  = (const float*)d_in[15];
    const float* b_ih  = (const float*)d_in[16];
    const float* b_hh  = (const float*)d_in[17];
    float* out = (float*)d_out;

    k_proj  <<<B * L1 + B * L2, 128>>>(x, y, Wup_w, Wup_b, Wq_w, Wq_b, Wvp_b);
    k_scores<<<dim3(L2 / 32, L1 / 32, B), dim3(32, 8)>>>(xmask, ymask, V_w, V_b);
    k_softmax<<<B * L1, 128>>>();
    k_fused <<<104, 512>>>(x, y, Wg_w, Wg_b, W_ih, b_ih, b_hh, W_hh, out);
}